// round 9
// baseline (speedup 1.0000x reference)
#include <cuda_runtime.h>
#include <stdint.h>

// FP32 bit-pulse -> FP8 E4M3 bit-pulse converter.
// Input:  N*32 floats, each 0.0/1.0, per value [S, E7..E0, M22..M0] (MSB first)
// Output: N*8  floats, per value [S, E3..E0, M2..M0]
//
// Structure (round-4 winner): lane l loads float (v*32 + l);
// __brev(__ballot(f > 0.5)) IS the IEEE-754 fp32 bit pattern of value v.
// Streaming hints (__ldcs/__stcs) keep the zero-reuse streams out of L2's way.
// Round-9: persistent grid-stride — grid sized to exact residency (148 SMs x 4
// blocks of 256 threads = one full wave); each warp loops over tiles with
// stride = total warp count. Removes ~8 wave transitions and per-block
// launch/drain overhead; inner body unchanged.

__global__ void __launch_bounds__(256)
fp32_to_fp8_pulse_kernel(const float* __restrict__ in,
                         float* __restrict__ out,
                         int ntiles)      // ntiles = nvals / 32
{
    const int lane        = threadIdx.x & 31;
    const int warp_global = (blockIdx.x * blockDim.x + threadIdx.x) >> 5;
    const int warp_count  = (gridDim.x * blockDim.x) >> 5;

    for (int tile = warp_global; tile < ntiles; tile += warp_count) {
        const int base = tile * 32;             // 32 values per tile
        const float* p = in + (size_t)base * 32;

        // Gather + ballot: iteration i reconstructs value (base + i); lane i keeps it.
        uint32_t word = 0;
#pragma unroll
        for (int i = 0; i < 32; i++) {
            float f = __ldcs(&p[i * 32 + lane]);    // streaming load, evict-first
            uint32_t b = __ballot_sync(0xFFFFFFFFu, f > 0.5f);
            if (lane == i) word = b;
        }
        word = __brev(word);   // standard IEEE fp32 bit pattern

        const uint32_t s    = word >> 31;
        const uint32_t exp  = (word >> 23) & 0xFFu;
        const uint32_t mant = word & 0x7FFFFFu;

        // ---- normal path: fp8_exp = exp - 120, RNE round 23 -> 3 mantissa bits ----
        uint32_t kept  = mant >> 20;
        uint32_t R     = (mant >> 19) & 1u;
        uint32_t S     = (mant & 0x7FFFFu) ? 1u : 0u;
        uint32_t L     = kept & 1u;
        uint32_t mr    = kept + (R & (S | L));
        uint32_t carry = mr >> 3;
        uint32_t mant_norm = carry ? 0u : (mr & 7u);
        int exp_norm = (int)exp - 120 + (int)carry;

        // ---- subnormal path (117 <= exp <= 120): shift 1.mant right, RNE ----
        uint32_t full = (1u << 23) | mant;
        int sh = 141 - (int)exp;
        sh = sh < 1 ? 1 : (sh > 24 ? 24 : sh);
        uint32_t kept_s = full >> sh;
        uint32_t Rs = (full >> (sh - 1)) & 1u;
        uint32_t Ss = (full & ((1u << (sh - 1)) - 1u)) ? 1u : 0u;
        uint32_t Ls = kept_s & 1u;
        uint32_t ms = kept_s + (Rs & (Ss | Ls));
        uint32_t sub_exp  = (ms >= 8u) ? 1u : 0u;
        uint32_t sub_mant = (ms >= 8u) ? 0u : ms;

        // ---- select overflow / subnormal / underflow / normal ----
        uint32_t exp8, mant8;
        if (exp > 134u) {
            exp8 = 15u; mant8 = 6u;
        } else if (exp >= 117u) {
            if (exp <= 120u) { exp8 = sub_exp; mant8 = sub_mant; }
            else             { exp8 = (uint32_t)exp_norm; mant8 = mant_norm; }
        } else {
            exp8 = 0u; mant8 = 0u;         // underflow
        }

        // ---- emit 8 bit-pulses: [S, E3..E0, M2..M0] ----
        float4 o0 = make_float4((float)s,
                                (float)((exp8 >> 3) & 1u),
                                (float)((exp8 >> 2) & 1u),
                                (float)((exp8 >> 1) & 1u));
        float4 o1 = make_float4((float)(exp8 & 1u),
                                (float)((mant8 >> 2) & 1u),
                                (float)((mant8 >> 1) & 1u),
                                (float)(mant8 & 1u));

        float4* op = reinterpret_cast<float4*>(out + (size_t)(base + lane) * 8);
        __stcs(&op[0], o0);    // streaming store
        __stcs(&op[1], o1);
    }
}

extern "C" void kernel_launch(void* const* d_in, const int* in_sizes, int n_in,
                              void* d_out, int out_size)
{
    const float* in  = (const float*)d_in[0];
    float*       out = (float*)d_out;
    const int nvals  = in_sizes[0] / 32;       // 2,097,152
    const int ntiles = nvals / 32;             // 65,536 warp tiles

    const int threads = 256;                   // 8 warps per block
    const int blocks  = 148 * 4;               // one full resident wave (32 warps/SM)

    fp32_to_fp8_pulse_kernel<<<blocks, threads>>>(in, out, ntiles);
}

// round 10
// speedup vs baseline: 4.3121x; 4.3121x over previous
#include <cuda_runtime.h>
#include <stdint.h>

// FP32 bit-pulse -> FP8 E4M3 bit-pulse converter.  FINAL (round-4 winner).
// Input:  N*32 floats, each 0.0/1.0, per value [S, E7..E0, M22..M0] (MSB first)
// Output: N*8  floats, per value [S, E3..E0, M2..M0]
//
// Lane l of the warp loads float (v*32 + l); __brev(__ballot(f > 0.5)) is
// exactly the IEEE-754 fp32 bit pattern of value v (S@31, E@30..23, M@22..0).
// Every warp load is one fully-consumed 128B line (minimal L1 wavefronts);
// __ldcs/__stcs keep the zero-reuse read/write streams from thrashing L2.
//
// Session findings (9 rounds): this shape runs at ~80% of HBM spec (6.4 TB/s)
// with all other pipes <50% and latency fully covered — the practical mixed
// 4:1 R/W HBM wall for this part. All structural alternatives regressed:
//  - per-thread 128B-stride loads  -> 32 L1tex wavefronts/instr, L1-bound (90%)
//  - two tiles per warp            -> ptxas re-serializes, ALU+L1 blowup
//  - smem transpose staging        -> occupancy loss + exposed phase latency
//  - cp.async.bulk double-buffer   -> consumer-starved at low occupancy
//  - persistent grid-stride loop   -> ptxas rolls the ballot loop, MLP=1 (4.7x)

__global__ void __launch_bounds__(256)
fp32_to_fp8_pulse_kernel(const float* __restrict__ in,
                         float* __restrict__ out,
                         int nvals)
{
    const int lane    = threadIdx.x & 31;
    const int warp_id = (blockIdx.x * blockDim.x + threadIdx.x) >> 5;
    const int base    = warp_id * 32;           // 32 values per warp
    if (base >= nvals) return;

    const float* p = in + (size_t)base * 32;

    // Gather + ballot: iteration i reconstructs value (base + i); lane i keeps it.
    uint32_t word = 0;
#pragma unroll
    for (int i = 0; i < 32; i++) {
        float f = __ldcs(&p[i * 32 + lane]);    // streaming load, evict-first
        uint32_t b = __ballot_sync(0xFFFFFFFFu, f > 0.5f);
        if (lane == i) word = b;
    }
    word = __brev(word);   // standard IEEE fp32 bit pattern

    const uint32_t s    = word >> 31;
    const uint32_t exp  = (word >> 23) & 0xFFu;
    const uint32_t mant = word & 0x7FFFFFu;

    // ---- normal path: fp8_exp = exp - 120, RNE round 23 -> 3 mantissa bits ----
    uint32_t kept  = mant >> 20;
    uint32_t R     = (mant >> 19) & 1u;
    uint32_t S     = (mant & 0x7FFFFu) ? 1u : 0u;
    uint32_t L     = kept & 1u;
    uint32_t mr    = kept + (R & (S | L));
    uint32_t carry = mr >> 3;
    uint32_t mant_norm = carry ? 0u : (mr & 7u);
    int exp_norm = (int)exp - 120 + (int)carry;

    // ---- subnormal path (117 <= exp <= 120): shift 1.mant right, RNE ----
    uint32_t full = (1u << 23) | mant;
    int sh = 141 - (int)exp;
    sh = sh < 1 ? 1 : (sh > 24 ? 24 : sh);
    uint32_t kept_s = full >> sh;
    uint32_t Rs = (full >> (sh - 1)) & 1u;
    uint32_t Ss = (full & ((1u << (sh - 1)) - 1u)) ? 1u : 0u;
    uint32_t Ls = kept_s & 1u;
    uint32_t ms = kept_s + (Rs & (Ss | Ls));
    uint32_t sub_exp  = (ms >= 8u) ? 1u : 0u;
    uint32_t sub_mant = (ms >= 8u) ? 0u : ms;

    // ---- select overflow / subnormal / underflow / normal ----
    uint32_t exp8, mant8;
    if (exp > 134u) {
        exp8 = 15u; mant8 = 6u;
    } else if (exp >= 117u) {
        if (exp <= 120u) { exp8 = sub_exp; mant8 = sub_mant; }
        else             { exp8 = (uint32_t)exp_norm; mant8 = mant_norm; }
    } else {
        exp8 = 0u; mant8 = 0u;         // underflow
    }

    // ---- emit 8 bit-pulses: [S, E3..E0, M2..M0] ----
    float4 o0 = make_float4((float)s,
                            (float)((exp8 >> 3) & 1u),
                            (float)((exp8 >> 2) & 1u),
                            (float)((exp8 >> 1) & 1u));
    float4 o1 = make_float4((float)(exp8 & 1u),
                            (float)((mant8 >> 2) & 1u),
                            (float)((mant8 >> 1) & 1u),
                            (float)(mant8 & 1u));

    float4* op = reinterpret_cast<float4*>(out + (size_t)(base + lane) * 8);
    __stcs(&op[0], o0);    // streaming store
    __stcs(&op[1], o1);
}

extern "C" void kernel_launch(void* const* d_in, const int* in_sizes, int n_in,
                              void* d_out, int out_size)
{
    const float* in  = (const float*)d_in[0];
    float*       out = (float*)d_out;
    const int nvals  = in_sizes[0] / 32;       // 2,097,152

    const int threads = 256;                   // 8 warps -> 256 values per block
    const int blocks = (nvals + threads - 1) / threads;

    fp32_to_fp8_pulse_kernel<<<blocks, threads>>>(in, out, nvals);
}

// round 13
// speedup vs baseline: 4.4264x; 1.0265x over previous
#include <cuda_runtime.h>
#include <stdint.h>

// FP32 bit-pulse -> FP8 E4M3 bit-pulse converter.  FINAL.
// Input:  N*32 floats, each 0.0/1.0, per value [S, E7..E0, M22..M0] (MSB first)
// Output: N*8  floats, per value [S, E3..E0, M2..M0]
//
// Lane l of the warp loads float (v*32 + l); __brev(__ballot(f > 0.5)) is
// exactly the IEEE-754 fp32 bit pattern of value v (S@31, E@30..23, M@22..0).
// Every warp load is one fully-consumed 128B line; __ldcs/__stcs keep the
// zero-reuse streams out of L2's way. Round-11: the two float4 stores are
// fused into one 256-bit st.global.cs.v8.f32 (sm_100+/CUDA 13), halving store
// issue slots; the load/ballot schedule is byte-identical to the winner.
//
// Session verdict: DRAM 80.9% (6.41 TB/s) with all other pipes <50% and
// ~2.4x the required bytes outstanding — this shape sits on the practical
// mixed 4:1 R/W HBM wall. Every structural alternative (per-thread layout,
// multi-tile, smem transpose, cp.async.bulk pipeline, persistent loop)
// regressed with understood causes.

__global__ void __launch_bounds__(256)
fp32_to_fp8_pulse_kernel(const float* __restrict__ in,
                         float* __restrict__ out,
                         int nvals)
{
    const int lane    = threadIdx.x & 31;
    const int warp_id = (blockIdx.x * blockDim.x + threadIdx.x) >> 5;
    const int base    = warp_id * 32;           // 32 values per warp
    if (base >= nvals) return;

    const float* p = in + (size_t)base * 32;

    // Gather + ballot: iteration i reconstructs value (base + i); lane i keeps it.
    uint32_t word = 0;
#pragma unroll
    for (int i = 0; i < 32; i++) {
        float f = __ldcs(&p[i * 32 + lane]);    // streaming load, evict-first
        uint32_t b = __ballot_sync(0xFFFFFFFFu, f > 0.5f);
        if (lane == i) word = b;
    }
    word = __brev(word);   // standard IEEE fp32 bit pattern

    const uint32_t s    = word >> 31;
    const uint32_t exp  = (word >> 23) & 0xFFu;
    const uint32_t mant = word & 0x7FFFFFu;

    // ---- normal path: fp8_exp = exp - 120, RNE round 23 -> 3 mantissa bits ----
    uint32_t kept  = mant >> 20;
    uint32_t R     = (mant >> 19) & 1u;
    uint32_t S     = (mant & 0x7FFFFu) ? 1u : 0u;
    uint32_t L     = kept & 1u;
    uint32_t mr    = kept + (R & (S | L));
    uint32_t carry = mr >> 3;
    uint32_t mant_norm = carry ? 0u : (mr & 7u);
    int exp_norm = (int)exp - 120 + (int)carry;

    // ---- subnormal path (117 <= exp <= 120): shift 1.mant right, RNE ----
    uint32_t full = (1u << 23) | mant;
    int sh = 141 - (int)exp;
    sh = sh < 1 ? 1 : (sh > 24 ? 24 : sh);
    uint32_t kept_s = full >> sh;
    uint32_t Rs = (full >> (sh - 1)) & 1u;
    uint32_t Ss = (full & ((1u << (sh - 1)) - 1u)) ? 1u : 0u;
    uint32_t Ls = kept_s & 1u;
    uint32_t ms = kept_s + (Rs & (Ss | Ls));
    uint32_t sub_exp  = (ms >= 8u) ? 1u : 0u;
    uint32_t sub_mant = (ms >= 8u) ? 0u : ms;

    // ---- select overflow / subnormal / underflow / normal ----
    uint32_t exp8, mant8;
    if (exp > 134u) {
        exp8 = 15u; mant8 = 6u;
    } else if (exp >= 117u) {
        if (exp <= 120u) { exp8 = sub_exp; mant8 = sub_mant; }
        else             { exp8 = (uint32_t)exp_norm; mant8 = mant_norm; }
    } else {
        exp8 = 0u; mant8 = 0u;         // underflow
    }

    // ---- emit 8 bit-pulses: [S, E3..E0, M2..M0] via one 256-bit store ----
    const float e3 = (float)((exp8 >> 3) & 1u);
    const float e2 = (float)((exp8 >> 2) & 1u);
    const float e1 = (float)((exp8 >> 1) & 1u);
    const float e0 = (float)(exp8 & 1u);
    const float m2 = (float)((mant8 >> 2) & 1u);
    const float m1 = (float)((mant8 >> 1) & 1u);
    const float m0 = (float)(mant8 & 1u);
    const float sf = (float)s;

    float* op = out + (size_t)(base + lane) * 8;   // 32B-aligned
    asm volatile("st.global.cs.v8.f32 [%0], {%1,%2,%3,%4,%5,%6,%7,%8};"
                 :: "l"(op), "f"(sf), "f"(e3), "f"(e2), "f"(e1),
                    "f"(e0), "f"(m2), "f"(m1), "f"(m0)
                 : "memory");
}

extern "C" void kernel_launch(void* const* d_in, const int* in_sizes, int n_in,
                              void* d_out, int out_size)
{
    const float* in  = (const float*)d_in[0];
    float*       out = (float*)d_out;
    const int nvals  = in_sizes[0] / 32;       // 2,097,152

    const int threads = 256;                   // 8 warps -> 256 values per block
    const int blocks = (nvals + threads - 1) / threads;

    fp32_to_fp8_pulse_kernel<<<blocks, threads>>>(in, out, nvals);
}